// round 12
// baseline (speedup 1.0000x reference)
#include <cuda_runtime.h>
#include <cuda_bf16.h>
#include <cstddef>

#define DD 128
#define MAXN 100000
#define MAXE 1000000
#define AST 72   // smem row stride (words): 36≡4 (mod 32) -> bank8 = 4*mr+q, conflict-free LDS.64 frags

// ---- scratch (no cudaMalloc allowed) ----
__device__ float g_aggr[(size_t)MAXN * DD];
__device__ float g_z1[(size_t)MAXN * DD];
__device__ float g_z2[(size_t)MAXN * DD];
__device__ int   g_idx[(size_t)2 * MAXE];
__device__ int   g_fmt;
__device__ int   g_cnt[MAXN];
__device__ int   g_off[MAXN + 1];
__device__ int   g_cur[MAXN];
__device__ int   g_srcl[MAXE];
__device__ int   g_bsum[512];
__device__ float g_sum[DD];
__device__ float g_sq[DD];
__device__ float g_s1[DD];
__device__ float g_c1[DD];
__device__ float g_sh[DD];
__device__ float g_ch[DD];

// permuted word index within an 8-word (16-k) chunk: fragment pairs become adjacent
__device__ __forceinline__ int wperm(int w) {
    return (w & ~7) | ((w & 3) << 1) | ((w >> 2) & 1);
}

// ---------------------------------------------------------------- edge fmt detect
__global__ void detect_kernel(const int* __restrict__ ei32, int E) {
    __shared__ int bad;
    if (threadIdx.x == 0) bad = 0;
    __syncthreads();
    long long e = (long long)(threadIdx.x + 1) * (2LL * E) / 66;
    if (ei32[2 * (e >> 1) + 1] != 0) bad = 1;
    __syncthreads();
    if (threadIdx.x == 0) g_fmt = !bad;
}
// convert + fused dst histogram (cnt must be zeroed before)
__global__ void convert_hist_kernel(const void* __restrict__ ei, int n2, int N, int E,
                                    int* __restrict__ cnt) {
    int i = blockIdx.x * blockDim.x + threadIdx.x;
    if (i >= n2) return;
    int v = g_fmt ? (int)((const long long*)ei)[i] : ((const int*)ei)[i];
    if (v < 0) v = 0;
    if (v >= N) v = N - 1;
    g_idx[i] = v;
    if (i >= E) atomicAdd(&cnt[v], 1);
}

// ---------------------------------------------------------------- CSR build
__global__ void zcnt_kernel(int* __restrict__ cnt, int N) {
    int i = blockIdx.x * blockDim.x + threadIdx.x;
    if (i < N) cnt[i] = 0;
}
__global__ void scan_block(const int* __restrict__ cnt, int n, int* __restrict__ part,
                           int* __restrict__ bsum) {
    __shared__ int s[256];
    int i = blockIdx.x * 256 + threadIdx.x;
    int v = (i < n) ? cnt[i] : 0;
    s[threadIdx.x] = v;
    __syncthreads();
    for (int d = 1; d < 256; d <<= 1) {
        int t = (threadIdx.x >= d) ? s[threadIdx.x - d] : 0;
        __syncthreads();
        s[threadIdx.x] += t;
        __syncthreads();
    }
    if (i < n) part[i] = s[threadIdx.x];
    if (threadIdx.x == 255) bsum[blockIdx.x] = s[255];
}
__global__ void scan_sums(int* __restrict__ bsum, int nb) {
    __shared__ int s[512];
    int v = (threadIdx.x < nb) ? bsum[threadIdx.x] : 0;
    s[threadIdx.x] = v;
    __syncthreads();
    for (int d = 1; d < 512; d <<= 1) {
        int t = (threadIdx.x >= d) ? s[threadIdx.x - d] : 0;
        __syncthreads();
        s[threadIdx.x] += t;
        __syncthreads();
    }
    if (threadIdx.x < nb) bsum[threadIdx.x] = s[threadIdx.x];
}
__global__ void scan_final(const int* __restrict__ part, const int* __restrict__ bsum,
                           const int* __restrict__ cnt, int n,
                           int* __restrict__ off, int* __restrict__ cur) {
    int i = blockIdx.x * 256 + threadIdx.x;
    if (i >= n) return;
    int add = (blockIdx.x > 0) ? bsum[blockIdx.x - 1] : 0;
    int v = part[i] + add;
    off[i + 1] = v;
    cur[i] = v - cnt[i];
    if (i == 0) off[0] = 0;
}
__global__ void fill_kernel(const int* __restrict__ idx, int E,
                            int* __restrict__ cur, int* __restrict__ srcl) {
    int e = blockIdx.x * blockDim.x + threadIdx.x;
    if (e >= E) return;
    int pos = atomicAdd(&cur[idx[E + e]], 1);
    srcl[pos] = idx[e];
}

// ---------------------------------------------------------------- aggregate (pull, warp/dst)
__global__ void aggregate_kernel(const float4* __restrict__ h,
                                 const int* __restrict__ off, const int* __restrict__ srcl,
                                 int N, float4* __restrict__ aggr,
                                 const float* __restrict__ sH, const float* __restrict__ cH,
                                 const float* __restrict__ epsP, int layer, int mode) {
    __shared__ float ss[DD], sc[DD];
    if (mode) {
        if (threadIdx.x < DD) { ss[threadIdx.x] = sH[threadIdx.x]; sc[threadIdx.x] = cH[threadIdx.x]; }
        __syncthreads();
    }
    int gw = (blockIdx.x * blockDim.x + threadIdx.x) >> 5;
    if (gw >= N) return;
    int lane = threadIdx.x & 31;
    int k = lane * 4;
    float ev = 1.0f + epsP[layer];
    float s0 = 0.f, s1 = 0.f, s2 = 0.f, s3 = 0.f, c0 = 0.f, c1 = 0.f, c2 = 0.f, c3 = 0.f;
    if (mode) {
        s0 = ss[k]; s1 = ss[k + 1]; s2 = ss[k + 2]; s3 = ss[k + 3];
        c0 = sc[k]; c1 = sc[k + 1]; c2 = sc[k + 2]; c3 = sc[k + 3];
    }

    float4 a = h[(size_t)gw * 32 + lane];
    if (mode) {
        a.x = fmaxf(fmaf(s0, a.x, c0), 0.f);
        a.y = fmaxf(fmaf(s1, a.y, c1), 0.f);
        a.z = fmaxf(fmaf(s2, a.z, c2), 0.f);
        a.w = fmaxf(fmaf(s3, a.w, c3), 0.f);
    }
    float4 acc = make_float4(ev * a.x, ev * a.y, ev * a.z, ev * a.w);

    int e = off[gw], eEnd = off[gw + 1];
    for (; e + 2 <= eEnd; e += 2) {
        int sA = srcl[e], sB = srcl[e + 1];
        float4 vA = h[(size_t)sA * 32 + lane];
        float4 vB = h[(size_t)sB * 32 + lane];
        if (mode) {
            vA.x = fmaf(s0, vA.x, c0); vA.y = fmaf(s1, vA.y, c1);
            vA.z = fmaf(s2, vA.z, c2); vA.w = fmaf(s3, vA.w, c3);
            vB.x = fmaf(s0, vB.x, c0); vB.y = fmaf(s1, vB.y, c1);
            vB.z = fmaf(s2, vB.z, c2); vB.w = fmaf(s3, vB.w, c3);
        }
        acc.x += fmaxf(vA.x, 0.f) + fmaxf(vB.x, 0.f);
        acc.y += fmaxf(vA.y, 0.f) + fmaxf(vB.y, 0.f);
        acc.z += fmaxf(vA.z, 0.f) + fmaxf(vB.z, 0.f);
        acc.w += fmaxf(vA.w, 0.f) + fmaxf(vB.w, 0.f);
    }
    if (e < eEnd) {
        int sA = srcl[e];
        float4 vA = h[(size_t)sA * 32 + lane];
        if (mode) {
            vA.x = fmaf(s0, vA.x, c0); vA.y = fmaf(s1, vA.y, c1);
            vA.z = fmaf(s2, vA.z, c2); vA.w = fmaf(s3, vA.w, c3);
        }
        acc.x += fmaxf(vA.x, 0.f);
        acc.y += fmaxf(vA.y, 0.f);
        acc.z += fmaxf(vA.z, 0.f);
        acc.w += fmaxf(vA.w, 0.f);
    }
    aggr[(size_t)gw * 32 + lane] = acc;
}

// ---------------------------------------------------------------- bf16-split mma helpers
__device__ __forceinline__ void bsplit2(float f0, float f1, unsigned& hi, unsigned& lo) {
    __nv_bfloat16 h0 = __float2bfloat16(f0), h1 = __float2bfloat16(f1);
    float r0 = f0 - __bfloat162float(h0), r1 = f1 - __bfloat162float(h1);
    __nv_bfloat16 l0 = __float2bfloat16(r0), l1 = __float2bfloat16(r1);
    hi = ((unsigned)__bfloat16_as_ushort(h1) << 16) | __bfloat16_as_ushort(h0);
    lo = ((unsigned)__bfloat16_as_ushort(l1) << 16) | __bfloat16_as_ushort(l0);
}
__device__ __forceinline__ void mma16(float* c, unsigned a0, unsigned a1, unsigned a2,
                                      unsigned a3, unsigned b0, unsigned b1) {
    asm volatile(
        "mma.sync.aligned.m16n8k16.row.col.f32.bf16.bf16.f32 "
        "{%0,%1,%2,%3},{%4,%5,%6,%7},{%8,%9},{%0,%1,%2,%3};"
        : "+f"(c[0]), "+f"(c[1]), "+f"(c[2]), "+f"(c[3])
        : "r"(a0), "r"(a1), "r"(a2), "r"(a3), "r"(b0), "r"(b1));
}

// ---------------------------------------------------------------- GEMM (persistent, bf16 3-pass,
// permuted LDS.64 layout, double-buffered A, single sync per tile)
// Z[row][j] = sum_k a(row,k) * W[j][k]   (bias dropped: absorbed by following BN)
// mode 0: a = Ab;  mode 2: a = relu(sIn*Ab+cIn)
__global__ void __launch_bounds__(512, 1) gemm_bf16(
    const float* __restrict__ Ab, const float* __restrict__ W,
    const float* __restrict__ sIn, const float* __restrict__ cIn,
    int mode, int M, int nTiles,
    float* __restrict__ Z, float* __restrict__ gsum, float* __restrict__ gsq) {
    extern __shared__ unsigned smu[];
    unsigned* Ah[2] = { smu, smu + 2 * 128 * AST };
    unsigned* Al[2] = { smu + 128 * AST, smu + 3 * 128 * AST };
    unsigned* Wh = smu + 4 * 128 * AST;
    unsigned* Wl = Wh + 128 * AST;
    float* csum = (float*)(Wl + 128 * AST);
    float* csq = csum + DD;

    const int tid = threadIdx.x;
    const int lane = tid & 31, w = tid >> 5;
    const int q = lane & 3, mr = lane >> 2;
    const int mw = (w & 7) * 16, nh = w >> 3;

    if (tid < DD) { csum[tid] = 0.f; csq[tid] = 0.f; }

    // W -> Wh/Wl (split bf16, permuted layout)
    {
        const float4* w4 = (const float4*)W;
#pragma unroll
        for (int i = 0; i < 8; i++) {
            int f = tid + i * 512;
            int n = f >> 5, c4 = f & 31;
            float4 v = w4[f];
            unsigned h0, l0, h1, l1;
            bsplit2(v.x, v.y, h0, l0);
            bsplit2(v.z, v.w, h1, l1);
            int base = n * AST;
            int p0 = base + wperm(2 * c4), p1 = base + wperm(2 * c4 + 1);
            Wh[p0] = h0; Wh[p1] = h1;
            Wl[p0] = l0; Wl[p1] = l1;
        }
    }
    const int k0 = 4 * (tid & 31);
    float s0 = 0.f, s1 = 0.f, s2 = 0.f, s3 = 0.f, cc0 = 0.f, cc1 = 0.f, cc2 = 0.f, cc3 = 0.f;
    if (mode == 2) {
        s0 = __ldg(sIn + k0); s1 = __ldg(sIn + k0 + 1);
        s2 = __ldg(sIn + k0 + 2); s3 = __ldg(sIn + k0 + 3);
        cc0 = __ldg(cIn + k0); cc1 = __ldg(cIn + k0 + 1);
        cc2 = __ldg(cIn + k0 + 2); cc3 = __ldg(cIn + k0 + 3);
    }

    float4 pf[8];
    auto prefetch = [&](int t) {
        size_t rowBase = (size_t)t << 7;
#pragma unroll
        for (int i = 0; i < 8; i++) {
            int f = tid + i * 512;
            int r = f >> 5, c4 = f & 31;
            size_t gr = rowBase + r;
            pf[i] = (gr < (size_t)M) ? *(const float4*)(Ab + gr * DD + c4 * 4)
                                     : make_float4(0.f, 0.f, 0.f, 0.f);
        }
    };
    auto splitStore = [&](int buf) {
#pragma unroll
        for (int i = 0; i < 8; i++) {
            int f = tid + i * 512;
            int r = f >> 5, c4 = f & 31;
            float4 v = pf[i];
            if (mode == 2) {
                v.x = fmaxf(fmaf(s0, v.x, cc0), 0.f);
                v.y = fmaxf(fmaf(s1, v.y, cc1), 0.f);
                v.z = fmaxf(fmaf(s2, v.z, cc2), 0.f);
                v.w = fmaxf(fmaf(s3, v.w, cc3), 0.f);
            }
            unsigned h0, l0, h1, l1;
            bsplit2(v.x, v.y, h0, l0);
            bsplit2(v.z, v.w, h1, l1);
            int base = r * AST;
            int p0 = base + wperm(2 * c4), p1 = base + wperm(2 * c4 + 1);
            Ah[buf][p0] = h0; Ah[buf][p1] = h1;
            Al[buf][p0] = l0; Al[buf][p1] = l1;
        }
    };

    int t0 = blockIdx.x;
    if (t0 < nTiles) { prefetch(t0); splitStore(0); }

    int parity = 0;
    for (int t = t0; t < nTiles; t += gridDim.x, parity ^= 1) {
        int tn = t + gridDim.x;
        __syncthreads();                      // buf[parity] stored; buf[parity^1] mma-drained
        if (tn < nTiles) prefetch(tn);        // LDGs in flight during mma

        const unsigned* ah = Ah[parity];
        const unsigned* al = Al[parity];

        float acc[8][4];
#pragma unroll
        for (int nt = 0; nt < 8; nt++)
#pragma unroll
            for (int j = 0; j < 4; j++) acc[nt][j] = 0.f;

#pragma unroll
        for (int kt = 0; kt < 8; kt++) {
            const int cb = kt * 8 + 2 * q;
            uint2 aH0 = *(const uint2*)(ah + (mw + mr) * AST + cb);       // (a0,a2)
            uint2 aH1 = *(const uint2*)(ah + (mw + mr + 8) * AST + cb);   // (a1,a3)
            uint2 aL0 = *(const uint2*)(al + (mw + mr) * AST + cb);
            uint2 aL1 = *(const uint2*)(al + (mw + mr + 8) * AST + cb);
#pragma unroll
            for (int nt = 0; nt < 8; nt++) {
                const int n = nh * 64 + nt * 8 + mr;
                uint2 bh = *(const uint2*)(Wh + n * AST + cb);
                uint2 bl = *(const uint2*)(Wl + n * AST + cb);
                mma16(acc[nt], aH0.x, aH1.x, aH0.y, aH1.y, bh.x, bh.y);
                mma16(acc[nt], aL0.x, aL1.x, aL0.y, aL1.y, bh.x, bh.y);
                mma16(acc[nt], aH0.x, aH1.x, aH0.y, aH1.y, bl.x, bl.y);
            }
        }

        // epilogue: store Z + per-column stats
        const int rowBase = t << 7;
        const int r0 = rowBase + mw + mr;
        const int r1 = r0 + 8;
        const bool ok0 = r0 < M, ok1 = r1 < M;
#pragma unroll
        for (int nt = 0; nt < 8; nt++) {
            int j0 = nh * 64 + nt * 8 + 2 * q;
            float v00 = acc[nt][0], v01 = acc[nt][1], v10 = acc[nt][2], v11 = acc[nt][3];
            if (ok0) *(float2*)(Z + (size_t)r0 * DD + j0) = make_float2(v00, v01);
            if (ok1) *(float2*)(Z + (size_t)r1 * DD + j0) = make_float2(v10, v11);
            float S0 = (ok0 ? v00 : 0.f) + (ok1 ? v10 : 0.f);
            float S1 = (ok0 ? v01 : 0.f) + (ok1 ? v11 : 0.f);
            float Q0 = (ok0 ? v00 * v00 : 0.f) + (ok1 ? v10 * v10 : 0.f);
            float Q1 = (ok0 ? v01 * v01 : 0.f) + (ok1 ? v11 * v11 : 0.f);
#pragma unroll
            for (int m = 4; m <= 16; m <<= 1) {
                S0 += __shfl_xor_sync(0xffffffff, S0, m);
                S1 += __shfl_xor_sync(0xffffffff, S1, m);
                Q0 += __shfl_xor_sync(0xffffffff, Q0, m);
                Q1 += __shfl_xor_sync(0xffffffff, Q1, m);
            }
            if (mr == 0) {
                atomicAdd(&csum[j0], S0);
                atomicAdd(&csum[j0 + 1], S1);
                atomicAdd(&csq[j0], Q0);
                atomicAdd(&csq[j0 + 1], Q1);
            }
        }
        if (tn < nTiles) splitStore(parity ^ 1);   // safe: other buf drained since last sync
    }
    __syncthreads();
    if (tid < DD) {
        atomicAdd(&gsum[tid], csum[tid]);
        atomicAdd(&gsq[tid], csq[tid]);
    }
}

// ---------------------------------------------------------------- BN finalize
__global__ void finalize_kernel(float* __restrict__ gsum, float* __restrict__ gsq,
                                const float* __restrict__ gamma, const float* __restrict__ beta,
                                float invM, float* __restrict__ sOut, float* __restrict__ cOut) {
    int j = threadIdx.x;
    float mean = gsum[j] * invM;
    float var = gsq[j] * invM - mean * mean;
    float s = gamma[j] * rsqrtf(var + 1e-5f);
    sOut[j] = s;
    cOut[j] = beta[j] - mean * s;
    gsum[j] = 0.f;
    gsq[j] = 0.f;
}

// ---------------------------------------------------------------- final apply
__global__ void apply_kernel(const float4* __restrict__ z, const float* __restrict__ s,
                             const float* __restrict__ c, float4* __restrict__ out, int n4) {
    int i = blockIdx.x * blockDim.x + threadIdx.x;
    if (i >= n4) return;
    int k = (i & 31) * 4;
    float4 v = z[i];
    out[i] = make_float4(fmaf(s[k + 0], v.x, c[k + 0]),
                         fmaf(s[k + 1], v.y, c[k + 1]),
                         fmaf(s[k + 2], v.z, c[k + 2]),
                         fmaf(s[k + 3], v.w, c[k + 3]));
}

// ---------------------------------------------------------------- launch
extern "C" void kernel_launch(void* const* d_in, const int* in_sizes, int n_in,
                              void* d_out, int out_size) {
    const float* x    = (const float*)d_in[0];
    const void*  ei   = d_in[1];
    const float* W1   = (const float*)d_in[2];
    const float* g1   = (const float*)d_in[4];
    const float* bt1  = (const float*)d_in[5];
    const float* W2   = (const float*)d_in[6];
    const float* epsv = (const float*)d_in[8];
    const float* gout = (const float*)d_in[9];
    const float* bout = (const float*)d_in[10];

    int N = in_sizes[0] / DD;
    int E = in_sizes[1] / 2;

    void* p;
    cudaGetSymbolAddress(&p, g_aggr); float* aggr = (float*)p;
    cudaGetSymbolAddress(&p, g_z1);   float* z1   = (float*)p;
    cudaGetSymbolAddress(&p, g_z2);   float* z2   = (float*)p;
    cudaGetSymbolAddress(&p, g_idx);  int*   idx  = (int*)p;
    cudaGetSymbolAddress(&p, g_cnt);  int*   cnt  = (int*)p;
    cudaGetSymbolAddress(&p, g_off);  int*   off  = (int*)p;
    cudaGetSymbolAddress(&p, g_cur);  int*   cur  = (int*)p;
    cudaGetSymbolAddress(&p, g_srcl); int*   srcl = (int*)p;
    cudaGetSymbolAddress(&p, g_bsum); int*   bsum = (int*)p;
    cudaGetSymbolAddress(&p, g_sum);  float* gsum = (float*)p;
    cudaGetSymbolAddress(&p, g_sq);   float* gsq  = (float*)p;
    cudaGetSymbolAddress(&p, g_s1);   float* s1   = (float*)p;
    cudaGetSymbolAddress(&p, g_c1);   float* c1   = (float*)p;
    cudaGetSymbolAddress(&p, g_sh);   float* sh   = (float*)p;
    cudaGetSymbolAddress(&p, g_ch);   float* ch   = (float*)p;

    constexpr int SMEM = (6 * 128 * AST + 2 * DD) * 4;   // 222208
    cudaFuncSetAttribute(gemm_bf16, cudaFuncAttributeMaxDynamicSharedMemorySize, SMEM);

    float invM = 1.0f / (float)N;
    int n4 = N * (DD / 4);
    int zb = (n4 + 255) / 256;
    int n2 = 2 * E;
    int cb = (n2 + 255) / 256;
    int eb = (E + 255) / 256;
    int nb = (N + 255) / 256;
    int ab = (N * 32 + 255) / 256;
    int nTiles = (N + 127) / 128;
    int gg = 148;

    detect_kernel<<<1, 64>>>((const int*)ei, E);
    zcnt_kernel<<<nb, 256>>>(cnt, N);
    convert_hist_kernel<<<cb, 256>>>(ei, n2, N, E, cnt);

    // CSR build (reused by both layers)
    scan_block<<<nb, 256>>>(cnt, N, cur, bsum);
    scan_sums<<<1, 512>>>(bsum, nb);
    scan_final<<<nb, 256>>>(cur, bsum, cnt, N, off, cur);
    fill_kernel<<<eb, 256>>>(idx, E, cur, srcl);

    // ---- layer 0 ----
    aggregate_kernel<<<ab, 256>>>((const float4*)x, off, srcl, N, (float4*)aggr,
                                  nullptr, nullptr, epsv, 0, 0);
    gemm_bf16<<<gg, 512, SMEM>>>(aggr, W1, nullptr, nullptr, 0, N, nTiles, z1, gsum, gsq);
    finalize_kernel<<<1, DD>>>(gsum, gsq, g1, bt1, invM, s1, c1);
    gemm_bf16<<<gg, 512, SMEM>>>(z1, W2, s1, c1, 2, N, nTiles, z2, gsum, gsq);
    finalize_kernel<<<1, DD>>>(gsum, gsq, gout, bout, invM, sh, ch);

    // ---- layer 1 ----
    aggregate_kernel<<<ab, 256>>>((const float4*)z2, off, srcl, N, (float4*)aggr,
                                  sh, ch, epsv, 1, 1);
    gemm_bf16<<<gg, 512, SMEM>>>(aggr, W1 + DD * DD, nullptr, nullptr, 0, N, nTiles, z1, gsum, gsq);
    finalize_kernel<<<1, DD>>>(gsum, gsq, g1 + DD, bt1 + DD, invM, s1, c1);
    gemm_bf16<<<gg, 512, SMEM>>>(z1, W2 + DD * DD, s1, c1, 2, N, nTiles, z2, gsum, gsq);
    finalize_kernel<<<1, DD>>>(gsum, gsq, gout + DD, bout + DD, invM, sh, ch);

    apply_kernel<<<zb, 256>>>((const float4*)z2, sh, ch, (float4*)d_out, n4);
}

// round 14
// speedup vs baseline: 1.0711x; 1.0711x over previous
#include <cuda_runtime.h>
#include <cuda_bf16.h>
#include <cstddef>

#define DD 128
#define MAXN 100000
#define MAXE 1000000
#define AST 68   // smem row stride in 32-bit words: 68%32==4 -> (4*mr+q) covers all banks

// ---- scratch (no cudaMalloc allowed) ----
__device__ float g_aggr[(size_t)MAXN * DD];
__device__ float g_z1[(size_t)MAXN * DD];
__device__ float g_z2[(size_t)MAXN * DD];
__device__ int   g_idx[(size_t)2 * MAXE];
__device__ int   g_fmt;
__device__ int   g_cnt[MAXN];
__device__ int   g_off[MAXN + 1];
__device__ int   g_cur[MAXN];
__device__ int   g_srcl[MAXE];
__device__ int   g_bsum[512];
__device__ float g_sum[DD];
__device__ float g_sq[DD];
__device__ float g_s1[DD];
__device__ float g_c1[DD];
__device__ float g_sh[DD];
__device__ float g_ch[DD];

// ---------------------------------------------------------------- edge fmt detect
__global__ void detect_kernel(const int* __restrict__ ei32, int E) {
    __shared__ int bad;
    if (threadIdx.x == 0) bad = 0;
    __syncthreads();
    long long e = (long long)(threadIdx.x + 1) * (2LL * E) / 66;
    if (ei32[2 * (e >> 1) + 1] != 0) bad = 1;
    __syncthreads();
    if (threadIdx.x == 0) g_fmt = !bad;
}
// convert + fused dst histogram (cnt zeroed before)
__global__ void convert_hist_kernel(const void* __restrict__ ei, int n2, int N, int E,
                                    int* __restrict__ cnt) {
    int i = blockIdx.x * blockDim.x + threadIdx.x;
    if (i >= n2) return;
    int v = g_fmt ? (int)((const long long*)ei)[i] : ((const int*)ei)[i];
    if (v < 0) v = 0;
    if (v >= N) v = N - 1;
    g_idx[i] = v;
    if (i >= E) atomicAdd(&cnt[v], 1);
}

// ---------------------------------------------------------------- CSR build
__global__ void zcnt_kernel(int* __restrict__ cnt, int N) {
    int i = blockIdx.x * blockDim.x + threadIdx.x;
    if (i < N) cnt[i] = 0;
}
__global__ void scan_block(const int* __restrict__ cnt, int n, int* __restrict__ part,
                           int* __restrict__ bsum) {
    __shared__ int s[256];
    int i = blockIdx.x * 256 + threadIdx.x;
    int v = (i < n) ? cnt[i] : 0;
    s[threadIdx.x] = v;
    __syncthreads();
    for (int d = 1; d < 256; d <<= 1) {
        int t = (threadIdx.x >= d) ? s[threadIdx.x - d] : 0;
        __syncthreads();
        s[threadIdx.x] += t;
        __syncthreads();
    }
    if (i < n) part[i] = s[threadIdx.x];
    if (threadIdx.x == 255) bsum[blockIdx.x] = s[255];
}
__global__ void scan_sums(int* __restrict__ bsum, int nb) {
    __shared__ int s[512];
    int v = (threadIdx.x < nb) ? bsum[threadIdx.x] : 0;
    s[threadIdx.x] = v;
    __syncthreads();
    for (int d = 1; d < 512; d <<= 1) {
        int t = (threadIdx.x >= d) ? s[threadIdx.x - d] : 0;
        __syncthreads();
        s[threadIdx.x] += t;
        __syncthreads();
    }
    if (threadIdx.x < nb) bsum[threadIdx.x] = s[threadIdx.x];
}
__global__ void scan_final(const int* __restrict__ part, const int* __restrict__ bsum,
                           const int* __restrict__ cnt, int n,
                           int* __restrict__ off, int* __restrict__ cur) {
    int i = blockIdx.x * 256 + threadIdx.x;
    if (i >= n) return;
    int add = (blockIdx.x > 0) ? bsum[blockIdx.x - 1] : 0;
    int v = part[i] + add;
    off[i + 1] = v;
    cur[i] = v - cnt[i];
    if (i == 0) off[0] = 0;
}
__global__ void fill_kernel(const int* __restrict__ idx, int E,
                            int* __restrict__ cur, int* __restrict__ srcl) {
    int e = blockIdx.x * blockDim.x + threadIdx.x;
    if (e >= E) return;
    int pos = atomicAdd(&cur[idx[E + e]], 1);
    srcl[pos] = idx[e];
}

// ---------------------------------------------------------------- aggregate (pull, warp/dst)
__global__ void aggregate_kernel(const float4* __restrict__ h,
                                 const int* __restrict__ off, const int* __restrict__ srcl,
                                 int N, float4* __restrict__ aggr,
                                 const float* __restrict__ sH, const float* __restrict__ cH,
                                 const float* __restrict__ epsP, int layer, int mode) {
    __shared__ float ss[DD], sc[DD];
    if (mode) {
        if (threadIdx.x < DD) { ss[threadIdx.x] = sH[threadIdx.x]; sc[threadIdx.x] = cH[threadIdx.x]; }
        __syncthreads();
    }
    int gw = (blockIdx.x * blockDim.x + threadIdx.x) >> 5;
    if (gw >= N) return;
    int lane = threadIdx.x & 31;
    int k = lane * 4;
    float ev = 1.0f + epsP[layer];
    float s0 = 0.f, s1 = 0.f, s2 = 0.f, s3 = 0.f, c0 = 0.f, c1 = 0.f, c2 = 0.f, c3 = 0.f;
    if (mode) {
        s0 = ss[k]; s1 = ss[k + 1]; s2 = ss[k + 2]; s3 = ss[k + 3];
        c0 = sc[k]; c1 = sc[k + 1]; c2 = sc[k + 2]; c3 = sc[k + 3];
    }

    float4 a = h[(size_t)gw * 32 + lane];
    if (mode) {
        a.x = fmaxf(fmaf(s0, a.x, c0), 0.f);
        a.y = fmaxf(fmaf(s1, a.y, c1), 0.f);
        a.z = fmaxf(fmaf(s2, a.z, c2), 0.f);
        a.w = fmaxf(fmaf(s3, a.w, c3), 0.f);
    }
    float4 acc = make_float4(ev * a.x, ev * a.y, ev * a.z, ev * a.w);

    int e = off[gw], eEnd = off[gw + 1];
    for (; e + 2 <= eEnd; e += 2) {
        int sA = srcl[e], sB = srcl[e + 1];
        float4 vA = h[(size_t)sA * 32 + lane];
        float4 vB = h[(size_t)sB * 32 + lane];
        if (mode) {
            vA.x = fmaf(s0, vA.x, c0); vA.y = fmaf(s1, vA.y, c1);
            vA.z = fmaf(s2, vA.z, c2); vA.w = fmaf(s3, vA.w, c3);
            vB.x = fmaf(s0, vB.x, c0); vB.y = fmaf(s1, vB.y, c1);
            vB.z = fmaf(s2, vB.z, c2); vB.w = fmaf(s3, vB.w, c3);
        }
        acc.x += fmaxf(vA.x, 0.f) + fmaxf(vB.x, 0.f);
        acc.y += fmaxf(vA.y, 0.f) + fmaxf(vB.y, 0.f);
        acc.z += fmaxf(vA.z, 0.f) + fmaxf(vB.z, 0.f);
        acc.w += fmaxf(vA.w, 0.f) + fmaxf(vB.w, 0.f);
    }
    if (e < eEnd) {
        int sA = srcl[e];
        float4 vA = h[(size_t)sA * 32 + lane];
        if (mode) {
            vA.x = fmaf(s0, vA.x, c0); vA.y = fmaf(s1, vA.y, c1);
            vA.z = fmaf(s2, vA.z, c2); vA.w = fmaf(s3, vA.w, c3);
        }
        acc.x += fmaxf(vA.x, 0.f);
        acc.y += fmaxf(vA.y, 0.f);
        acc.z += fmaxf(vA.z, 0.f);
        acc.w += fmaxf(vA.w, 0.f);
    }
    aggr[(size_t)gw * 32 + lane] = acc;
}

// ---------------------------------------------------------------- bf16-split mma helpers
__device__ __forceinline__ void bsplit2(float f0, float f1, unsigned& hi, unsigned& lo) {
    __nv_bfloat16 h0 = __float2bfloat16(f0), h1 = __float2bfloat16(f1);
    float r0 = f0 - __bfloat162float(h0), r1 = f1 - __bfloat162float(h1);
    __nv_bfloat16 l0 = __float2bfloat16(r0), l1 = __float2bfloat16(r1);
    hi = ((unsigned)__bfloat16_as_ushort(h1) << 16) | __bfloat16_as_ushort(h0);
    lo = ((unsigned)__bfloat16_as_ushort(l1) << 16) | __bfloat16_as_ushort(l0);
}
__device__ __forceinline__ void mma16(float* c, unsigned a0, unsigned a1, unsigned a2,
                                      unsigned a3, unsigned b0, unsigned b1) {
    asm volatile(
        "mma.sync.aligned.m16n8k16.row.col.f32.bf16.bf16.f32 "
        "{%0,%1,%2,%3},{%4,%5,%6,%7},{%8,%9},{%0,%1,%2,%3};"
        : "+f"(c[0]), "+f"(c[1]), "+f"(c[2]), "+f"(c[3])
        : "r"(a0), "r"(a1), "r"(a2), "r"(a3), "r"(b0), "r"(b1));
}

// ---------------------------------------------------------------- GEMM (persistent, bf16 3-pass)
// Z[row][j] = sum_k a(row,k) * W[j][k]   (bias dropped: absorbed by following BN)
// mode 0: a = Ab;  mode 2: a = relu(sIn*Ab+cIn)
__global__ void __launch_bounds__(512, 1) gemm_bf16(
    const float* __restrict__ Ab, const float* __restrict__ W,
    const float* __restrict__ sIn, const float* __restrict__ cIn,
    int mode, int M, int nTiles,
    float* __restrict__ Z, float* __restrict__ gsum, float* __restrict__ gsq) {
    extern __shared__ unsigned smu[];
    unsigned* Ah = smu;
    unsigned* Al = Ah + 128 * AST;
    unsigned* Wh = Al + 128 * AST;
    unsigned* Wl = Wh + 128 * AST;
    float* csum = (float*)(Wl + 128 * AST);
    float* csq = csum + DD;

    const int tid = threadIdx.x;
    const int lane = tid & 31, w = tid >> 5;
    const int q = lane & 3, mr = lane >> 2;
    const int mw = (w & 7) * 16, nh = w >> 3;

    if (tid < DD) { csum[tid] = 0.f; csq[tid] = 0.f; }

    // W -> Wh/Wl (split bf16, stride AST)
    {
        const float4* w4 = (const float4*)W;
#pragma unroll
        for (int i = 0; i < 8; i++) {
            int f = tid + i * 512;
            int n = f >> 5, c4 = f & 31;
            float4 v = w4[f];
            unsigned h0, l0, h1, l1;
            bsplit2(v.x, v.y, h0, l0);
            bsplit2(v.z, v.w, h1, l1);
            int off = n * AST + 2 * c4;
            *(uint2*)(Wh + off) = make_uint2(h0, h1);
            *(uint2*)(Wl + off) = make_uint2(l0, l1);
        }
    }
    const int k0 = 4 * (tid & 31);
    float s0 = 0.f, s1 = 0.f, s2 = 0.f, s3 = 0.f, cc0 = 0.f, cc1 = 0.f, cc2 = 0.f, cc3 = 0.f;
    if (mode == 2) {
        s0 = __ldg(sIn + k0); s1 = __ldg(sIn + k0 + 1);
        s2 = __ldg(sIn + k0 + 2); s3 = __ldg(sIn + k0 + 3);
        cc0 = __ldg(cIn + k0); cc1 = __ldg(cIn + k0 + 1);
        cc2 = __ldg(cIn + k0 + 2); cc3 = __ldg(cIn + k0 + 3);
    }

    float4 pf[8];
    auto prefetch = [&](int t) {
        size_t rowBase = (size_t)t << 7;
#pragma unroll
        for (int i = 0; i < 8; i++) {
            int f = tid + i * 512;
            int r = f >> 5, c4 = f & 31;
            size_t gr = rowBase + r;
            pf[i] = (gr < (size_t)M) ? *(const float4*)(Ab + gr * DD + c4 * 4)
                                     : make_float4(0.f, 0.f, 0.f, 0.f);
        }
    };

    int tIdx = blockIdx.x;
    if (tIdx < nTiles) prefetch(tIdx);

    for (; tIdx < nTiles; tIdx += gridDim.x) {
        __syncthreads();   // previous tile's compute done reading A smem
        // store A (pre-op + split)
#pragma unroll
        for (int i = 0; i < 8; i++) {
            int f = tid + i * 512;
            int r = f >> 5;
            float4 v = pf[i];
            if (mode == 2) {
                v.x = fmaxf(fmaf(s0, v.x, cc0), 0.f);
                v.y = fmaxf(fmaf(s1, v.y, cc1), 0.f);
                v.z = fmaxf(fmaf(s2, v.z, cc2), 0.f);
                v.w = fmaxf(fmaf(s3, v.w, cc3), 0.f);
            }
            unsigned h0, l0, h1, l1;
            bsplit2(v.x, v.y, h0, l0);
            bsplit2(v.z, v.w, h1, l1);
            int off = r * AST + 2 * (tid & 31);
            *(uint2*)(Ah + off) = make_uint2(h0, h1);
            *(uint2*)(Al + off) = make_uint2(l0, l1);
        }
        __syncthreads();   // A ready
        int rowBase = tIdx << 7;
        if (tIdx + (int)gridDim.x < nTiles) prefetch(tIdx + gridDim.x);   // overlap DRAM w/ mma

        float acc[8][4];
#pragma unroll
        for (int nt = 0; nt < 8; nt++)
#pragma unroll
            for (int j = 0; j < 4; j++) acc[nt][j] = 0.f;

#pragma unroll
        for (int kt = 0; kt < 8; kt++) {
            const int c8 = kt * 8;
            const unsigned* ar = Ah + (mw + mr) * AST + c8 + q;
            unsigned ah0 = ar[0], ah1 = ar[8 * AST], ah2 = ar[4], ah3 = ar[8 * AST + 4];
            const unsigned* al = Al + (mw + mr) * AST + c8 + q;
            unsigned aL0 = al[0], aL1 = al[8 * AST], aL2 = al[4], aL3 = al[8 * AST + 4];
#pragma unroll
            for (int nt = 0; nt < 8; nt++) {
                const int n = nh * 64 + nt * 8 + mr;
                const unsigned* whp = Wh + n * AST + c8 + q;
                unsigned bh0 = whp[0], bh1 = whp[4];
                const unsigned* wlp = Wl + n * AST + c8 + q;
                unsigned bl0 = wlp[0], bl1 = wlp[4];
                mma16(acc[nt], ah0, ah1, ah2, ah3, bh0, bh1);
                mma16(acc[nt], aL0, aL1, aL2, aL3, bh0, bh1);
                mma16(acc[nt], ah0, ah1, ah2, ah3, bl0, bl1);
            }
        }

        // epilogue: store Z + per-column stats
        const int r0 = rowBase + mw + mr;
        const int r1 = r0 + 8;
        const bool ok0 = r0 < M, ok1 = r1 < M;
#pragma unroll
        for (int nt = 0; nt < 8; nt++) {
            int j0 = nh * 64 + nt * 8 + 2 * q;
            float v00 = acc[nt][0], v01 = acc[nt][1], v10 = acc[nt][2], v11 = acc[nt][3];
            if (ok0) *(float2*)(Z + (size_t)r0 * DD + j0) = make_float2(v00, v01);
            if (ok1) *(float2*)(Z + (size_t)r1 * DD + j0) = make_float2(v10, v11);
            float S0 = (ok0 ? v00 : 0.f) + (ok1 ? v10 : 0.f);
            float S1 = (ok0 ? v01 : 0.f) + (ok1 ? v11 : 0.f);
            float Q0 = (ok0 ? v00 * v00 : 0.f) + (ok1 ? v10 * v10 : 0.f);
            float Q1 = (ok0 ? v01 * v01 : 0.f) + (ok1 ? v11 * v11 : 0.f);
#pragma unroll
            for (int m = 4; m <= 16; m <<= 1) {
                S0 += __shfl_xor_sync(0xffffffff, S0, m);
                S1 += __shfl_xor_sync(0xffffffff, S1, m);
                Q0 += __shfl_xor_sync(0xffffffff, Q0, m);
                Q1 += __shfl_xor_sync(0xffffffff, Q1, m);
            }
            if (mr == 0) {
                atomicAdd(&csum[j0], S0);
                atomicAdd(&csum[j0 + 1], S1);
                atomicAdd(&csq[j0], Q0);
                atomicAdd(&csq[j0 + 1], Q1);
            }
        }
    }
    __syncthreads();
    if (tid < DD) {
        atomicAdd(&gsum[tid], csum[tid]);
        atomicAdd(&gsq[tid], csq[tid]);
    }
}

// ---------------------------------------------------------------- BN finalize
__global__ void finalize_kernel(float* __restrict__ gsum, float* __restrict__ gsq,
                                const float* __restrict__ gamma, const float* __restrict__ beta,
                                float invM, float* __restrict__ sOut, float* __restrict__ cOut) {
    int j = threadIdx.x;
    float mean = gsum[j] * invM;
    float var = gsq[j] * invM - mean * mean;
    float s = gamma[j] * rsqrtf(var + 1e-5f);
    sOut[j] = s;
    cOut[j] = beta[j] - mean * s;
    gsum[j] = 0.f;
    gsq[j] = 0.f;
}

// ---------------------------------------------------------------- final apply
__global__ void apply_kernel(const float4* __restrict__ z, const float* __restrict__ s,
                             const float* __restrict__ c, float4* __restrict__ out, int n4) {
    int i = blockIdx.x * blockDim.x + threadIdx.x;
    if (i >= n4) return;
    int k = (i & 31) * 4;
    float4 v = z[i];
    out[i] = make_float4(fmaf(s[k + 0], v.x, c[k + 0]),
                         fmaf(s[k + 1], v.y, c[k + 1]),
                         fmaf(s[k + 2], v.z, c[k + 2]),
                         fmaf(s[k + 3], v.w, c[k + 3]));
}

// ---------------------------------------------------------------- launch
extern "C" void kernel_launch(void* const* d_in, const int* in_sizes, int n_in,
                              void* d_out, int out_size) {
    const float* x    = (const float*)d_in[0];
    const void*  ei   = d_in[1];
    const float* W1   = (const float*)d_in[2];
    const float* g1   = (const float*)d_in[4];
    const float* bt1  = (const float*)d_in[5];
    const float* W2   = (const float*)d_in[6];
    const float* epsv = (const float*)d_in[8];
    const float* gout = (const float*)d_in[9];
    const float* bout = (const float*)d_in[10];

    int N = in_sizes[0] / DD;
    int E = in_sizes[1] / 2;

    void* p;
    cudaGetSymbolAddress(&p, g_aggr); float* aggr = (float*)p;
    cudaGetSymbolAddress(&p, g_z1);   float* z1   = (float*)p;
    cudaGetSymbolAddress(&p, g_z2);   float* z2   = (float*)p;
    cudaGetSymbolAddress(&p, g_idx);  int*   idx  = (int*)p;
    cudaGetSymbolAddress(&p, g_cnt);  int*   cnt  = (int*)p;
    cudaGetSymbolAddress(&p, g_off);  int*   off  = (int*)p;
    cudaGetSymbolAddress(&p, g_cur);  int*   cur  = (int*)p;
    cudaGetSymbolAddress(&p, g_srcl); int*   srcl = (int*)p;
    cudaGetSymbolAddress(&p, g_bsum); int*   bsum = (int*)p;
    cudaGetSymbolAddress(&p, g_sum);  float* gsum = (float*)p;
    cudaGetSymbolAddress(&p, g_sq);   float* gsq  = (float*)p;
    cudaGetSymbolAddress(&p, g_s1);   float* s1   = (float*)p;
    cudaGetSymbolAddress(&p, g_c1);   float* c1   = (float*)p;
    cudaGetSymbolAddress(&p, g_sh);   float* sh   = (float*)p;
    cudaGetSymbolAddress(&p, g_ch);   float* ch   = (float*)p;

    constexpr int SMEM = (4 * 128 * AST + 2 * DD) * 4;   // 140288
    cudaFuncSetAttribute(gemm_bf16, cudaFuncAttributeMaxDynamicSharedMemorySize, SMEM);

    float invM = 1.0f / (float)N;
    int n4 = N * (DD / 4);
    int zb = (n4 + 255) / 256;
    int n2 = 2 * E;
    int cb = (n2 + 255) / 256;
    int eb = (E + 255) / 256;
    int nb = (N + 255) / 256;
    int ab = (N * 32 + 255) / 256;
    int nTiles = (N + 127) / 128;
    int gg = 148;

    detect_kernel<<<1, 64>>>((const int*)ei, E);
    zcnt_kernel<<<nb, 256>>>(cnt, N);
    convert_hist_kernel<<<cb, 256>>>(ei, n2, N, E, cnt);

    // CSR build (reused by both layers)
    scan_block<<<nb, 256>>>(cnt, N, cur, bsum);
    scan_sums<<<1, 512>>>(bsum, nb);
    scan_final<<<nb, 256>>>(cur, bsum, cnt, N, off, cur);
    fill_kernel<<<eb, 256>>>(idx, E, cur, srcl);

    // ---- layer 0 ----
    aggregate_kernel<<<ab, 256>>>((const float4*)x, off, srcl, N, (float4*)aggr,
                                  nullptr, nullptr, epsv, 0, 0);
    gemm_bf16<<<gg, 512, SMEM>>>(aggr, W1, nullptr, nullptr, 0, N, nTiles, z1, gsum, gsq);
    finalize_kernel<<<1, DD>>>(gsum, gsq, g1, bt1, invM, s1, c1);
    gemm_bf16<<<gg, 512, SMEM>>>(z1, W2, s1, c1, 2, N, nTiles, z2, gsum, gsq);
    finalize_kernel<<<1, DD>>>(gsum, gsq, gout, bout, invM, sh, ch);

    // ---- layer 1 ----
    aggregate_kernel<<<ab, 256>>>((const float4*)z2, off, srcl, N, (float4*)aggr,
                                  sh, ch, epsv, 1, 1);
    gemm_bf16<<<gg, 512, SMEM>>>(aggr, W1 + DD * DD, nullptr, nullptr, 0, N, nTiles, z1, gsum, gsq);
    finalize_kernel<<<1, DD>>>(gsum, gsq, g1 + DD, bt1 + DD, invM, s1, c1);
    gemm_bf16<<<gg, 512, SMEM>>>(z1, W2 + DD * DD, s1, c1, 2, N, nTiles, z2, gsum, gsq);
    finalize_kernel<<<1, DD>>>(gsum, gsq, gout + DD, bout + DD, invM, sh, ch);

    apply_kernel<<<zb, 256>>>((const float4*)z2, sh, ch, (float4*)d_out, n4);
}

// round 15
// speedup vs baseline: 1.2637x; 1.1798x over previous
#include <cuda_runtime.h>
#include <cuda_bf16.h>
#include <cstddef>
#include <cstdint>

#define DD 128
#define MAXN 100000
#define MAXE 1000000
#define AST 68    // W smem stride (words), proven R10 config
#define FST 136   // fp32 A-staging stride (words): 136/2=68≡4 mod 16 -> optimal 2-phase LDS.64

// ---- scratch (no cudaMalloc allowed) ----
__device__ float g_aggr[(size_t)MAXN * DD];
__device__ float g_z1[(size_t)MAXN * DD];
__device__ float g_z2[(size_t)MAXN * DD];
__device__ int   g_idx[(size_t)2 * MAXE];
__device__ int   g_fmt;
__device__ int   g_cnt[MAXN];
__device__ int   g_off[MAXN + 1];
__device__ int   g_cur[MAXN];
__device__ int   g_srcl[MAXE];
__device__ int   g_bsum[512];
__device__ float g_sum[DD];
__device__ float g_sq[DD];
__device__ float g_s1[DD];
__device__ float g_c1[DD];
__device__ float g_sh[DD];
__device__ float g_ch[DD];

// ---------------------------------------------------------------- edge fmt detect
__global__ void detect_kernel(const int* __restrict__ ei32, int E) {
    __shared__ int bad;
    if (threadIdx.x == 0) bad = 0;
    __syncthreads();
    long long e = (long long)(threadIdx.x + 1) * (2LL * E) / 66;
    if (ei32[2 * (e >> 1) + 1] != 0) bad = 1;
    __syncthreads();
    if (threadIdx.x == 0) g_fmt = !bad;
}
// convert + fused dst histogram (cnt zeroed before)
__global__ void convert_hist_kernel(const void* __restrict__ ei, int n2, int N, int E,
                                    int* __restrict__ cnt) {
    int i = blockIdx.x * blockDim.x + threadIdx.x;
    if (i >= n2) return;
    int v = g_fmt ? (int)((const long long*)ei)[i] : ((const int*)ei)[i];
    if (v < 0) v = 0;
    if (v >= N) v = N - 1;
    g_idx[i] = v;
    if (i >= E) atomicAdd(&cnt[v], 1);
}

// ---------------------------------------------------------------- CSR build
__global__ void zcnt_kernel(int* __restrict__ cnt, int N) {
    int i = blockIdx.x * blockDim.x + threadIdx.x;
    if (i < N) cnt[i] = 0;
}
__global__ void scan_block(const int* __restrict__ cnt, int n, int* __restrict__ part,
                           int* __restrict__ bsum) {
    __shared__ int s[256];
    int i = blockIdx.x * 256 + threadIdx.x;
    int v = (i < n) ? cnt[i] : 0;
    s[threadIdx.x] = v;
    __syncthreads();
    for (int d = 1; d < 256; d <<= 1) {
        int t = (threadIdx.x >= d) ? s[threadIdx.x - d] : 0;
        __syncthreads();
        s[threadIdx.x] += t;
        __syncthreads();
    }
    if (i < n) part[i] = s[threadIdx.x];
    if (threadIdx.x == 255) bsum[blockIdx.x] = s[255];
}
__global__ void scan_sums(int* __restrict__ bsum, int nb) {
    __shared__ int s[512];
    int v = (threadIdx.x < nb) ? bsum[threadIdx.x] : 0;
    s[threadIdx.x] = v;
    __syncthreads();
    for (int d = 1; d < 512; d <<= 1) {
        int t = (threadIdx.x >= d) ? s[threadIdx.x - d] : 0;
        __syncthreads();
        s[threadIdx.x] += t;
        __syncthreads();
    }
    if (threadIdx.x < nb) bsum[threadIdx.x] = s[threadIdx.x];
}
__global__ void scan_final(const int* __restrict__ part, const int* __restrict__ bsum,
                           const int* __restrict__ cnt, int n,
                           int* __restrict__ off, int* __restrict__ cur) {
    int i = blockIdx.x * 256 + threadIdx.x;
    if (i >= n) return;
    int add = (blockIdx.x > 0) ? bsum[blockIdx.x - 1] : 0;
    int v = part[i] + add;
    off[i + 1] = v;
    cur[i] = v - cnt[i];
    if (i == 0) off[0] = 0;
}
__global__ void fill_kernel(const int* __restrict__ idx, int E,
                            int* __restrict__ cur, int* __restrict__ srcl) {
    int e = blockIdx.x * blockDim.x + threadIdx.x;
    if (e >= E) return;
    int pos = atomicAdd(&cur[idx[E + e]], 1);
    srcl[pos] = idx[e];
}

// ---------------------------------------------------------------- aggregate (pull, warp/dst)
__global__ void aggregate_kernel(const float4* __restrict__ h,
                                 const int* __restrict__ off, const int* __restrict__ srcl,
                                 int N, float4* __restrict__ aggr,
                                 const float* __restrict__ sH, const float* __restrict__ cH,
                                 const float* __restrict__ epsP, int layer, int mode) {
    __shared__ float ss[DD], sc[DD];
    if (mode) {
        if (threadIdx.x < DD) { ss[threadIdx.x] = sH[threadIdx.x]; sc[threadIdx.x] = cH[threadIdx.x]; }
        __syncthreads();
    }
    int gw = (blockIdx.x * blockDim.x + threadIdx.x) >> 5;
    if (gw >= N) return;
    int lane = threadIdx.x & 31;
    int k = lane * 4;
    float ev = 1.0f + epsP[layer];
    float s0 = 0.f, s1 = 0.f, s2 = 0.f, s3 = 0.f, c0 = 0.f, c1 = 0.f, c2 = 0.f, c3 = 0.f;
    if (mode) {
        s0 = ss[k]; s1 = ss[k + 1]; s2 = ss[k + 2]; s3 = ss[k + 3];
        c0 = sc[k]; c1 = sc[k + 1]; c2 = sc[k + 2]; c3 = sc[k + 3];
    }

    float4 a = h[(size_t)gw * 32 + lane];
    if (mode) {
        a.x = fmaxf(fmaf(s0, a.x, c0), 0.f);
        a.y = fmaxf(fmaf(s1, a.y, c1), 0.f);
        a.z = fmaxf(fmaf(s2, a.z, c2), 0.f);
        a.w = fmaxf(fmaf(s3, a.w, c3), 0.f);
    }
    float4 acc = make_float4(ev * a.x, ev * a.y, ev * a.z, ev * a.w);

    int e = off[gw], eEnd = off[gw + 1];
    for (; e + 2 <= eEnd; e += 2) {
        int sA = srcl[e], sB = srcl[e + 1];
        float4 vA = h[(size_t)sA * 32 + lane];
        float4 vB = h[(size_t)sB * 32 + lane];
        if (mode) {
            vA.x = fmaf(s0, vA.x, c0); vA.y = fmaf(s1, vA.y, c1);
            vA.z = fmaf(s2, vA.z, c2); vA.w = fmaf(s3, vA.w, c3);
            vB.x = fmaf(s0, vB.x, c0); vB.y = fmaf(s1, vB.y, c1);
            vB.z = fmaf(s2, vB.z, c2); vB.w = fmaf(s3, vB.w, c3);
        }
        acc.x += fmaxf(vA.x, 0.f) + fmaxf(vB.x, 0.f);
        acc.y += fmaxf(vA.y, 0.f) + fmaxf(vB.y, 0.f);
        acc.z += fmaxf(vA.z, 0.f) + fmaxf(vB.z, 0.f);
        acc.w += fmaxf(vA.w, 0.f) + fmaxf(vB.w, 0.f);
    }
    if (e < eEnd) {
        int sA = srcl[e];
        float4 vA = h[(size_t)sA * 32 + lane];
        if (mode) {
            vA.x = fmaf(s0, vA.x, c0); vA.y = fmaf(s1, vA.y, c1);
            vA.z = fmaf(s2, vA.z, c2); vA.w = fmaf(s3, vA.w, c3);
        }
        acc.x += fmaxf(vA.x, 0.f);
        acc.y += fmaxf(vA.y, 0.f);
        acc.z += fmaxf(vA.z, 0.f);
        acc.w += fmaxf(vA.w, 0.f);
    }
    aggr[(size_t)gw * 32 + lane] = acc;
}

// ---------------------------------------------------------------- bf16-split mma helpers
__device__ __forceinline__ void bsplit2(float f0, float f1, unsigned& hi, unsigned& lo) {
    __nv_bfloat16 h0 = __float2bfloat16(f0), h1 = __float2bfloat16(f1);
    float r0 = f0 - __bfloat162float(h0), r1 = f1 - __bfloat162float(h1);
    __nv_bfloat16 l0 = __float2bfloat16(r0), l1 = __float2bfloat16(r1);
    hi = ((unsigned)__bfloat16_as_ushort(h1) << 16) | __bfloat16_as_ushort(h0);
    lo = ((unsigned)__bfloat16_as_ushort(l1) << 16) | __bfloat16_as_ushort(l0);
}
__device__ __forceinline__ void mma16(float* c, unsigned a0, unsigned a1, unsigned a2,
                                      unsigned a3, unsigned b0, unsigned b1) {
    asm volatile(
        "mma.sync.aligned.m16n8k16.row.col.f32.bf16.bf16.f32 "
        "{%0,%1,%2,%3},{%4,%5,%6,%7},{%8,%9},{%0,%1,%2,%3};"
        : "+f"(c[0]), "+f"(c[1]), "+f"(c[2]), "+f"(c[3])
        : "r"(a0), "r"(a1), "r"(a2), "r"(a3), "r"(b0), "r"(b1));
}
__device__ __forceinline__ uint32_t smem_u32(const void* p) {
    uint32_t a;
    asm("{ .reg .u64 t; cvta.to.shared.u64 t, %1; cvt.u32.u64 %0, t; }" : "=r"(a) : "l"(p));
    return a;
}
__device__ __forceinline__ void cpasync16(uint32_t dst, const void* src, int sz) {
    asm volatile("cp.async.cg.shared.global [%0], [%1], 16, %2;"
                 :: "r"(dst), "l"(src), "r"(sz) : "memory");
}

// ---------------------------------------------------------------- GEMM
// persistent, cp.async double-buffered fp32 staging, inline bf16 split, register BN stats
// Z[row][j] = sum_k a(row,k) * W[j][k]   (bias dropped: absorbed by following BN)
// mode 0: a = Ab;  mode 2: a = relu(sIn*Ab+cIn)
__global__ void __launch_bounds__(512, 1) gemm_bf16(
    const float* __restrict__ Ab, const float* __restrict__ W,
    const float* __restrict__ sIn, const float* __restrict__ cIn,
    int mode, int M, int nTiles,
    float* __restrict__ Z, float* __restrict__ gsum, float* __restrict__ gsq) {
    extern __shared__ unsigned smu[];
    float* Af0 = (float*)smu;
    float* Af1 = (float*)(smu + 128 * FST);
    unsigned* Wh = smu + 2 * 128 * FST;
    unsigned* Wl = Wh + 128 * AST;
    float* csum = (float*)(Wl + 128 * AST);
    float* csq = csum + DD;
    float* ssk = csq + DD;    // affine scale (mode 2)
    float* sck = ssk + DD;    // affine shift

    const int tid = threadIdx.x;
    const int lane = tid & 31, w = tid >> 5;
    const int q = lane & 3, mr = lane >> 2;
    const int mw = (w & 7) * 16, nh = w >> 3;

    if (tid < DD) {
        csum[tid] = 0.f;
        csq[tid] = 0.f;
        if (mode == 2) { ssk[tid] = sIn[tid]; sck[tid] = cIn[tid]; }
    }

    // W -> Wh/Wl (split bf16, stride AST)
    {
        const float4* w4 = (const float4*)W;
#pragma unroll
        for (int i = 0; i < 8; i++) {
            int f = tid + i * 512;
            int n = f >> 5, c4 = f & 31;
            float4 v = w4[f];
            unsigned h0, l0, h1, l1;
            bsplit2(v.x, v.y, h0, l0);
            bsplit2(v.z, v.w, h1, l1);
            int off = n * AST + 2 * c4;
            *(uint2*)(Wh + off) = make_uint2(h0, h1);
            *(uint2*)(Wl + off) = make_uint2(l0, l1);
        }
    }

    const uint32_t afBase[2] = { smem_u32(Af0), smem_u32(Af1) };
    auto issueTile = [&](int t, int buf) {
        size_t rowBase = (size_t)t << 7;
#pragma unroll
        for (int i = 0; i < 8; i++) {
            int f = tid + i * 512;
            int r = f >> 5, c4 = f & 31;
            size_t gr = rowBase + r;
            bool ok = gr < (size_t)M;
            const float* src = Ab + (ok ? gr * DD + c4 * 4 : 0);
            cpasync16(afBase[buf] + (r * FST + c4 * 4) * 4, src, ok ? 16 : 0);
        }
        asm volatile("cp.async.commit_group;" ::: "memory");
    };

    // running BN stats (registers, flushed once at end)
    float rS0[8], rS1[8], rQ0[8], rQ1[8];
#pragma unroll
    for (int nt = 0; nt < 8; nt++) { rS0[nt] = 0.f; rS1[nt] = 0.f; rQ0[nt] = 0.f; rQ1[nt] = 0.f; }

    int t = blockIdx.x;
    if (t < nTiles) issueTile(t, 0);
    int parity = 0;

    for (; t < nTiles; t += gridDim.x, parity ^= 1) {
        asm volatile("cp.async.wait_group 0;" ::: "memory");
        __syncthreads();                              // staged tile visible to all warps
        int tn = t + gridDim.x;
        if (tn < nTiles) issueTile(tn, parity ^ 1);   // overlaps mma below

        const float* A = parity ? Af1 : Af0;

        float acc[8][4];
#pragma unroll
        for (int nt = 0; nt < 8; nt++)
#pragma unroll
            for (int j = 0; j < 4; j++) acc[nt][j] = 0.f;

#pragma unroll
        for (int kt = 0; kt < 8; kt++) {
            const int kw = kt * 16 + 2 * q;          // fp32 word offset (covers k=kw,kw+1)
            float2 f0 = *(const float2*)(A + (mw + mr) * FST + kw);
            float2 f1 = *(const float2*)(A + (mw + mr + 8) * FST + kw);
            float2 f2 = *(const float2*)(A + (mw + mr) * FST + kw + 8);
            float2 f3 = *(const float2*)(A + (mw + mr + 8) * FST + kw + 8);
            if (mode == 2) {
                float2 sA = *(const float2*)(ssk + kw), cA = *(const float2*)(sck + kw);
                float2 sB = *(const float2*)(ssk + kw + 8), cB = *(const float2*)(sck + kw + 8);
                f0.x = fmaxf(fmaf(sA.x, f0.x, cA.x), 0.f);
                f0.y = fmaxf(fmaf(sA.y, f0.y, cA.y), 0.f);
                f1.x = fmaxf(fmaf(sA.x, f1.x, cA.x), 0.f);
                f1.y = fmaxf(fmaf(sA.y, f1.y, cA.y), 0.f);
                f2.x = fmaxf(fmaf(sB.x, f2.x, cB.x), 0.f);
                f2.y = fmaxf(fmaf(sB.y, f2.y, cB.y), 0.f);
                f3.x = fmaxf(fmaf(sB.x, f3.x, cB.x), 0.f);
                f3.y = fmaxf(fmaf(sB.y, f3.y, cB.y), 0.f);
            }
            unsigned ah0, al0, ah1, al1, ah2, al2, ah3, al3;
            bsplit2(f0.x, f0.y, ah0, al0);
            bsplit2(f1.x, f1.y, ah1, al1);
            bsplit2(f2.x, f2.y, ah2, al2);
            bsplit2(f3.x, f3.y, ah3, al3);
            const int c8 = kt * 8;
#pragma unroll
            for (int nt = 0; nt < 8; nt++) {
                const int n = nh * 64 + nt * 8 + mr;
                const unsigned* whp = Wh + n * AST + c8 + q;
                unsigned bh0 = whp[0], bh1 = whp[4];
                const unsigned* wlp = Wl + n * AST + c8 + q;
                unsigned bl0 = wlp[0], bl1 = wlp[4];
                mma16(acc[nt], ah0, ah1, ah2, ah3, bh0, bh1);
                mma16(acc[nt], al0, al1, al2, al3, bh0, bh1);
                mma16(acc[nt], ah0, ah1, ah2, ah3, bl0, bl1);
            }
        }

        // epilogue: store Z, accumulate stats in registers
        const int rowBase = t << 7;
        const int r0 = rowBase + mw + mr;
        const int r1 = r0 + 8;
        const bool ok0 = r0 < M, ok1 = r1 < M;
#pragma unroll
        for (int nt = 0; nt < 8; nt++) {
            int j0 = nh * 64 + nt * 8 + 2 * q;
            float v00 = acc[nt][0], v01 = acc[nt][1], v10 = acc[nt][2], v11 = acc[nt][3];
            if (ok0) {
                *(float2*)(Z + (size_t)r0 * DD + j0) = make_float2(v00, v01);
                rS0[nt] += v00; rS1[nt] += v01;
                rQ0[nt] = fmaf(v00, v00, rQ0[nt]); rQ1[nt] = fmaf(v01, v01, rQ1[nt]);
            }
            if (ok1) {
                *(float2*)(Z + (size_t)r1 * DD + j0) = make_float2(v10, v11);
                rS0[nt] += v10; rS1[nt] += v11;
                rQ0[nt] = fmaf(v10, v10, rQ0[nt]); rQ1[nt] = fmaf(v11, v11, rQ1[nt]);
            }
        }
    }

    // flush stats once: reduce over mr (lanes xor 4,8,16), then smem, then global
#pragma unroll
    for (int nt = 0; nt < 8; nt++) {
        float S0 = rS0[nt], S1 = rS1[nt], Q0 = rQ0[nt], Q1 = rQ1[nt];
#pragma unroll
        for (int m = 4; m <= 16; m <<= 1) {
            S0 += __shfl_xor_sync(0xffffffff, S0, m);
            S1 += __shfl_xor_sync(0xffffffff, S1, m);
            Q0 += __shfl_xor_sync(0xffffffff, Q0, m);
            Q1 += __shfl_xor_sync(0xffffffff, Q1, m);
        }
        if (mr == 0) {
            int j0 = nh * 64 + nt * 8 + 2 * q;
            atomicAdd(&csum[j0], S0);
            atomicAdd(&csum[j0 + 1], S1);
            atomicAdd(&csq[j0], Q0);
            atomicAdd(&csq[j0 + 1], Q1);
        }
    }
    __syncthreads();
    if (tid < DD) {
        atomicAdd(&gsum[tid], csum[tid]);
        atomicAdd(&gsq[tid], csq[tid]);
    }
}

// ---------------------------------------------------------------- BN finalize
__global__ void finalize_kernel(float* __restrict__ gsum, float* __restrict__ gsq,
                                const float* __restrict__ gamma, const float* __restrict__ beta,
                                float invM, float* __restrict__ sOut, float* __restrict__ cOut) {
    int j = threadIdx.x;
    float mean = gsum[j] * invM;
    float var = gsq[j] * invM - mean * mean;
    float s = gamma[j] * rsqrtf(var + 1e-5f);
    sOut[j] = s;
    cOut[j] = beta[j] - mean * s;
    gsum[j] = 0.f;
    gsq[j] = 0.f;
}

// ---------------------------------------------------------------- final apply
__global__ void apply_kernel(const float4* __restrict__ z, const float* __restrict__ s,
                             const float* __restrict__ c, float4* __restrict__ out, int n4) {
    int i = blockIdx.x * blockDim.x + threadIdx.x;
    if (i >= n4) return;
    int k = (i & 31) * 4;
    float4 v = z[i];
    out[i] = make_float4(fmaf(s[k + 0], v.x, c[k + 0]),
                         fmaf(s[k + 1], v.y, c[k + 1]),
                         fmaf(s[k + 2], v.z, c[k + 2]),
                         fmaf(s[k + 3], v.w, c[k + 3]));
}

// ---------------------------------------------------------------- launch
extern "C" void kernel_launch(void* const* d_in, const int* in_sizes, int n_in,
                              void* d_out, int out_size) {
    const float* x    = (const float*)d_in[0];
    const void*  ei   = d_in[1];
    const float* W1   = (const float*)d_in[2];
    const float* g1   = (const float*)d_in[4];
    const float* bt1  = (const float*)d_in[5];
    const float* W2   = (const float*)d_in[6];
    const float* epsv = (const float*)d_in[8];
    const float* gout = (const float*)d_in[9];
    const float* bout = (const float*)d_in[10];

    int N = in_sizes[0] / DD;
    int E = in_sizes[1] / 2;

    void* p;
    cudaGetSymbolAddress(&p, g_aggr); float* aggr = (float*)p;
    cudaGetSymbolAddress(&p, g_z1);   float* z1   = (float*)p;
    cudaGetSymbolAddress(&p, g_z2);   float* z2   = (float*)p;
    cudaGetSymbolAddress(&p, g_idx);  int*   idx  = (int*)p;
    cudaGetSymbolAddress(&p, g_cnt);  int*   cnt  = (int*)p;
    cudaGetSymbolAddress(&p, g_off);  int*   off  = (int*)p;
    cudaGetSymbolAddress(&p, g_cur);  int*   cur  = (int*)p;
    cudaGetSymbolAddress(&p, g_srcl); int*   srcl = (int*)p;
    cudaGetSymbolAddress(&p, g_bsum); int*   bsum = (int*)p;
    cudaGetSymbolAddress(&p, g_sum);  float* gsum = (float*)p;
    cudaGetSymbolAddress(&p, g_sq);   float* gsq  = (float*)p;
    cudaGetSymbolAddress(&p, g_s1);   float* s1   = (float*)p;
    cudaGetSymbolAddress(&p, g_c1);   float* c1   = (float*)p;
    cudaGetSymbolAddress(&p, g_sh);   float* sh   = (float*)p;
    cudaGetSymbolAddress(&p, g_ch);   float* ch   = (float*)p;

    constexpr int SMEM = (2 * 128 * FST + 2 * 128 * AST + 4 * DD) * 4;   // 210944
    cudaFuncSetAttribute(gemm_bf16, cudaFuncAttributeMaxDynamicSharedMemorySize, SMEM);

    float invM = 1.0f / (float)N;
    int n4 = N * (DD / 4);
    int zb = (n4 + 255) / 256;
    int n2 = 2 * E;
    int cb = (n2 + 255) / 256;
    int eb = (E + 255) / 256;
    int nb = (N + 255) / 256;
    int ab = (N * 32 + 255) / 256;
    int nTiles = (N + 127) / 128;
    int gg = 148;

    detect_kernel<<<1, 64>>>((const int*)ei, E);
    zcnt_kernel<<<nb, 256>>>(cnt, N);
    convert_hist_kernel<<<cb, 256>>>(ei, n2, N, E, cnt);

    // CSR build (reused by both layers)
    scan_block<<<nb, 256>>>(cnt, N, cur, bsum);
    scan_sums<<<1, 512>>>(bsum, nb);
    scan_final<<<nb, 256>>>(cur, bsum, cnt, N, off, cur);
    fill_kernel<<<eb, 256>>>(idx, E, cur, srcl);

    // ---- layer 0 ----
    aggregate_kernel<<<ab, 256>>>((const float4*)x, off, srcl, N, (float4*)aggr,
                                  nullptr, nullptr, epsv, 0, 0);
    gemm_bf16<<<gg, 512, SMEM>>>(aggr, W1, nullptr, nullptr, 0, N, nTiles, z1, gsum, gsq);
    finalize_kernel<<<1, DD>>>(gsum, gsq, g1, bt1, invM, s1, c1);
    gemm_bf16<<<gg, 512, SMEM>>>(z1, W2, s1, c1, 2, N, nTiles, z2, gsum, gsq);
    finalize_kernel<<<1, DD>>>(gsum, gsq, gout, bout, invM, sh, ch);

    // ---- layer 1 ----
    aggregate_kernel<<<ab, 256>>>((const float4*)z2, off, srcl, N, (float4*)aggr,
                                  sh, ch, epsv, 1, 1);
    gemm_bf16<<<gg, 512, SMEM>>>(aggr, W1 + DD * DD, nullptr, nullptr, 0, N, nTiles, z1, gsum, gsq);
    finalize_kernel<<<1, DD>>>(gsum, gsq, g1 + DD, bt1 + DD, invM, s1, c1);
    gemm_bf16<<<gg, 512, SMEM>>>(z1, W2 + DD * DD, s1, c1, 2, N, nTiles, z2, gsum, gsq);
    finalize_kernel<<<1, DD>>>(gsum, gsq, gout + DD, bout + DD, invM, sh, ch);

    apply_kernel<<<zb, 256>>>((const float4*)z2, sh, ch, (float4*)d_out, n4);
}